// round 1
// baseline (speedup 1.0000x reference)
#include <cuda_runtime.h>
#include <math_constants.h>
#include <cstdint>

#define BB   8
#define CCH  192
#define OUTC 384
#define NN   3136            // H*W = 56*56
#define KNB  16
#define MTOT (BB*NN)         // 25088
#define NT64 (NN/64)         // 49 tiles per dim
#define NPAIR ((NT64*(NT64+1))/2)   // 1225 upper-tri tile pairs
#define MB64 (MTOT/64)       // 392

// ---------------- device scratch (no allocs allowed) ----------------
__device__ float g_xt[(size_t)BB*NN*CCH];          // (B,N,C) transposed features
__device__ float g_x2[BB*NN];                      // row squared norms
__device__ float g_dist[(size_t)BB*NN*NN];         // 315 MB distance matrix
__device__ int   g_idx[(size_t)BB*NN*KNB];         // top-K neighbor indices
__device__ float g_feat[(size_t)BB*NN*2*CCH];      // interleaved (x, maxrel)
__device__ float g_y[(size_t)BB*NN*OUTC];          // pre-BN conv output
__device__ float g_psum[MB64*OUTC];                // BN partial sums
__device__ float g_psq[MB64*OUTC];                 // BN partial sumsq
__device__ float g_scale[OUTC];
__device__ float g_shift[OUTC];

// ---------------- 1) transpose x (B,C,N) -> xt (B,N,C) ----------------
__global__ void k_transpose(const float* __restrict__ x) {
    __shared__ float tile[32][33];
    int b  = blockIdx.z;
    int n0 = blockIdx.x * 32, c0 = blockIdx.y * 32;
    int tx = threadIdx.x, ty = threadIdx.y;
    tile[ty][tx] = x[((size_t)b*CCH + c0 + ty)*NN + n0 + tx];
    __syncthreads();
    g_xt[((size_t)b*NN + n0 + ty)*CCH + c0 + tx] = tile[tx][ty];
}

// ---------------- 2) row squared norms ----------------
__global__ void k_x2() {
    int row  = blockIdx.x * 8 + (threadIdx.x >> 5);
    int lane = threadIdx.x & 31;
    const float* p = g_xt + (size_t)row * CCH;
    float s = 0.f;
    for (int c = lane; c < CCH; c += 32) { float v = p[c]; s += v * v; }
    #pragma unroll
    for (int o = 16; o; o >>= 1) s += __shfl_down_sync(0xffffffffu, s, o);
    if (lane == 0) g_x2[row] = s;
}

// ---------------- 3) symmetric distance GEMM ----------------
// 64x64 tile, 128 threads, 8x4 microtile. Upper-triangular tile pairs only;
// mirror half written via shared-memory transpose (coalesced both ways).
__global__ void k_dist() {
    int b = blockIdx.y;
    int p = blockIdx.x;
    int ti = 0, rem = p;
    while (rem >= NT64 - ti) { rem -= NT64 - ti; ti++; }
    int tj = ti + rem;
    int i0 = ti * 64, j0 = tj * 64;

    __shared__ __align__(16) float As[16][64];
    __shared__ __align__(16) float Bs[16][64];
    __shared__ float Ts[64][65];

    int tid = threadIdx.x;
    int tx = tid & 15, ty = tid >> 4;

    float acc[8][4];
    #pragma unroll
    for (int r = 0; r < 8; r++)
        #pragma unroll
        for (int c = 0; c < 4; c++) acc[r][c] = 0.f;

    const float* xa = g_xt + (size_t)b * NN * CCH;

    for (int kk = 0; kk < CCH; kk += 16) {
        #pragma unroll
        for (int e = 0; e < 2; e++) {
            int q = tid + e * 128;
            int m = q >> 2, k4 = (q & 3) << 2;
            float4 va = *(const float4*)(xa + (size_t)(i0 + m)*CCH + kk + k4);
            As[k4+0][m] = va.x; As[k4+1][m] = va.y; As[k4+2][m] = va.z; As[k4+3][m] = va.w;
            float4 vb = *(const float4*)(xa + (size_t)(j0 + m)*CCH + kk + k4);
            Bs[k4+0][m] = vb.x; Bs[k4+1][m] = vb.y; Bs[k4+2][m] = vb.z; Bs[k4+3][m] = vb.w;
        }
        __syncthreads();
        #pragma unroll
        for (int k = 0; k < 16; k++) {
            float4 a0 = *(const float4*)&As[k][ty*8];
            float4 a1 = *(const float4*)&As[k][ty*8+4];
            float4 b0 = *(const float4*)&Bs[k][tx*4];
            float a[8] = {a0.x,a0.y,a0.z,a0.w,a1.x,a1.y,a1.z,a1.w};
            float bv[4] = {b0.x,b0.y,b0.z,b0.w};
            #pragma unroll
            for (int r = 0; r < 8; r++)
                #pragma unroll
                for (int c = 0; c < 4; c++) acc[r][c] += a[r]*bv[c];
        }
        __syncthreads();
    }

    float x2i[8], x2j[4];
    #pragma unroll
    for (int r = 0; r < 8; r++) x2i[r] = g_x2[b*NN + i0 + ty*8 + r];
    #pragma unroll
    for (int c = 0; c < 4; c++) x2j[c] = g_x2[b*NN + j0 + tx*4 + c];

    #pragma unroll
    for (int r = 0; r < 8; r++) {
        #pragma unroll
        for (int c = 0; c < 4; c++) {
            float d = x2i[r] + x2j[c] - 2.f * acc[r][c];
            g_dist[((size_t)b*NN + i0 + ty*8 + r)*NN + j0 + tx*4 + c] = d;
            Ts[tx*4 + c][ty*8 + r] = d;
        }
    }
    if (ti != tj) {
        __syncthreads();
        #pragma unroll
        for (int e = 0; e < 32; e++) {
            int q = tid + e * 128;
            int r = q >> 6, cc = q & 63;
            g_dist[((size_t)b*NN + j0 + r)*NN + i0 + cc] = Ts[r][cc];
        }
    }
}

// ---------------- 4) top-K smallest per row (warp per row) ----------------
__global__ void k_topk() {
    __shared__ float sv[8][32][16];
    __shared__ int   si[8][32][16];
    int w = threadIdx.x >> 5, lane = threadIdx.x & 31;
    int row = blockIdx.x * 8 + w;
    const float* dr = g_dist + (size_t)row * NN;
    float* mv = sv[w][lane];
    int*   mi = si[w][lane];

    #pragma unroll
    for (int s = 0; s < 16; s++) { mv[s] = CUDART_INF_F; mi[s] = 0; }
    float worst = CUDART_INF_F; int wslot = 0;

    for (int t = lane; t < NN; t += 32) {
        float d = dr[t];
        if (d < worst) {
            mv[wslot] = d; mi[wslot] = t;
            float mw = mv[0]; int ms = 0;
            #pragma unroll
            for (int s = 1; s < 16; s++) { float v = mv[s]; if (v > mw) { mw = v; ms = s; } }
            worst = mw; wslot = ms;
        }
    }
    // 16-round merge: global argmin over 32 lane-local lists
    for (int k = 0; k < KNB; k++) {
        float lv = mv[0]; int lpos = 0;
        #pragma unroll
        for (int s = 1; s < 16; s++) { float v = mv[s]; if (v < lv) { lv = v; lpos = s; } }
        int lidx = mi[lpos];
        float bv = lv; int bl = lane;
        #pragma unroll
        for (int o = 16; o; o >>= 1) {
            float ov = __shfl_down_sync(0xffffffffu, bv, o);
            int   ol = __shfl_down_sync(0xffffffffu, bl, o);
            if (ov < bv) { bv = ov; bl = ol; }
        }
        bl = __shfl_sync(0xffffffffu, bl, 0);
        int widx = __shfl_sync(0xffffffffu, lidx, bl);
        if (lane == bl) mv[lpos] = CUDART_INF_F;
        if (lane == 0) g_idx[(size_t)row*KNB + k] = widx;
    }
}

// ---------------- 5) gather + max-relative + interleaved feat ----------------
__global__ void k_feat() {
    __shared__ int ji[KNB];
    int m = blockIdx.x;          // b*N + n
    int c = threadIdx.x;         // 192 threads
    if (c < KNB) ji[c] = g_idx[(size_t)m*KNB + c];
    __syncthreads();
    int b = m / NN;
    const float* xb = g_xt + (size_t)b * NN * CCH;
    float xc = g_xt[(size_t)m*CCH + c];
    float mx = -CUDART_INF_F;
    #pragma unroll
    for (int k = 0; k < KNB; k++) {
        float v = xb[(size_t)ji[k]*CCH + c];
        mx = fmaxf(mx, v - xc);
    }
    float2 o; o.x = xc; o.y = mx;
    *(float2*)&g_feat[(size_t)m*(2*CCH) + 2*c] = o;
}

// ---------------- 6) y = feat @ w^T + bias ----------------
__global__ void k_gemm2(const float* __restrict__ w, const float* __restrict__ bias) {
    int m0 = blockIdx.x * 64;
    int o0 = blockIdx.y * 64;
    __shared__ __align__(16) float As[16][64];
    __shared__ __align__(16) float Bs[16][64];
    int tid = threadIdx.x;
    int tx = tid & 15, ty = tid >> 4;
    float acc[8][4];
    #pragma unroll
    for (int r = 0; r < 8; r++)
        #pragma unroll
        for (int c = 0; c < 4; c++) acc[r][c] = 0.f;

    for (int kk = 0; kk < 2*CCH; kk += 16) {
        #pragma unroll
        for (int e = 0; e < 2; e++) {
            int q = tid + e * 128;
            int m = q >> 2, k4 = (q & 3) << 2;
            float4 va = *(const float4*)(g_feat + (size_t)(m0 + m)*(2*CCH) + kk + k4);
            As[k4+0][m] = va.x; As[k4+1][m] = va.y; As[k4+2][m] = va.z; As[k4+3][m] = va.w;
            float4 vb = *(const float4*)(w + (size_t)(o0 + m)*(2*CCH) + kk + k4);
            Bs[k4+0][m] = vb.x; Bs[k4+1][m] = vb.y; Bs[k4+2][m] = vb.z; Bs[k4+3][m] = vb.w;
        }
        __syncthreads();
        #pragma unroll
        for (int k = 0; k < 16; k++) {
            float4 a0 = *(const float4*)&As[k][ty*8];
            float4 a1 = *(const float4*)&As[k][ty*8+4];
            float4 b0 = *(const float4*)&Bs[k][tx*4];
            float a[8] = {a0.x,a0.y,a0.z,a0.w,a1.x,a1.y,a1.z,a1.w};
            float bv[4] = {b0.x,b0.y,b0.z,b0.w};
            #pragma unroll
            for (int r = 0; r < 8; r++)
                #pragma unroll
                for (int c = 0; c < 4; c++) acc[r][c] += a[r]*bv[c];
        }
        __syncthreads();
    }
    #pragma unroll
    for (int r = 0; r < 8; r++) {
        #pragma unroll
        for (int c = 0; c < 4; c++) {
            int o = o0 + tx*4 + c;
            g_y[(size_t)(m0 + ty*8 + r)*OUTC + o] = acc[r][c] + bias[o];
        }
    }
}

// ---------------- 7) BN partial sums (deterministic, no atomics) ----------------
__global__ void k_bnpart() {
    int o  = threadIdx.x;        // 384 threads
    int m0 = blockIdx.x * 64;    // 392 blocks
    float s = 0.f, q = 0.f;
    for (int r = 0; r < 64; r++) {
        float v = g_y[(size_t)(m0 + r)*OUTC + o];
        s += v; q += v * v;
    }
    g_psum[blockIdx.x*OUTC + o] = s;
    g_psq [blockIdx.x*OUTC + o] = q;
}

// ---------------- 8) BN finalize -> scale/shift ----------------
__global__ void k_bnfin(const float* __restrict__ gamma, const float* __restrict__ beta) {
    __shared__ float ss[256], sq[256];
    int o = blockIdx.x, t = threadIdx.x;
    float s = 0.f, q = 0.f;
    for (int p = t; p < MB64; p += 256) { s += g_psum[p*OUTC + o]; q += g_psq[p*OUTC + o]; }
    ss[t] = s; sq[t] = q; __syncthreads();
    for (int st = 128; st; st >>= 1) {
        if (t < st) { ss[t] += ss[t+st]; sq[t] += sq[t+st]; }
        __syncthreads();
    }
    if (t == 0) {
        float mean = ss[0] / (float)MTOT;
        float var  = sq[0] / (float)MTOT - mean*mean;
        float rs   = rsqrtf(var + 1e-5f);
        float sc   = gamma[o] * rs;
        g_scale[o] = sc;
        g_shift[o] = beta[o] - mean * sc;
    }
}

// ---------------- 9) normalize + ReLU + transpose to (B,OUT,N) ----------------
__global__ void k_out(float* __restrict__ out) {
    __shared__ float tile[32][33];
    int b  = blockIdx.z;
    int n0 = blockIdx.x * 32, o0 = blockIdx.y * 32;
    int tx = threadIdx.x, ty = threadIdx.y;
    int o = o0 + tx;
    float v = g_y[(size_t)(b*NN + n0 + ty)*OUTC + o];
    v = v * g_scale[o] + g_shift[o];
    tile[ty][tx] = fmaxf(v, 0.f);
    __syncthreads();
    out[((size_t)b*OUTC + o0 + ty)*NN + n0 + tx] = tile[tx][ty];
}

// ---------------- launch ----------------
extern "C" void kernel_launch(void* const* d_in, const int* in_sizes, int n_in,
                              void* d_out, int out_size) {
    const float* x     = (const float*)d_in[0];
    const float* w     = (const float*)d_in[1];
    const float* bias  = (const float*)d_in[2];
    const float* gamma = (const float*)d_in[3];
    const float* beta  = (const float*)d_in[4];
    float* out = (float*)d_out;

    dim3 tposeGrid(NN/32, CCH/32, BB);
    k_transpose<<<tposeGrid, dim3(32,32)>>>(x);
    k_x2<<<MTOT/8, 256>>>();
    k_dist<<<dim3(NPAIR, BB), 128>>>();
    k_topk<<<MTOT/8, 256>>>();
    k_feat<<<MTOT, CCH>>>();
    k_gemm2<<<dim3(MTOT/64, OUTC/64), 128>>>(w, bias);
    k_bnpart<<<MB64, OUTC>>>();
    k_bnfin<<<OUTC, 256>>>(gamma, beta);
    k_out<<<dim3(NN/32, OUTC/32, BB), dim3(32,32)>>>(out);
}

// round 4
// speedup vs baseline: 1.4488x; 1.4488x over previous
#include <cuda_runtime.h>
#include <math_constants.h>
#include <cstdint>

#define BB   8
#define CCH  192
#define OUTC 384
#define NN   3136            // H*W = 56*56
#define KNB  16
#define MTOT (BB*NN)         // 25088
#define NT64 (NN/64)         // 49 tiles per dim
#define NPAIR ((NT64*(NT64+1))/2)   // 1225 upper-tri tile pairs
#define MB64 (MTOT/64)       // 392
#define QCAP 512             // per-warp candidate queue capacity
#define FULLM 0xffffffffu

// ---------------- device scratch (no allocs allowed) ----------------
__device__ float g_xt[(size_t)BB*NN*CCH];          // (B,N,C) transposed features
__device__ float g_x2[BB*NN];                      // row squared norms
__device__ float g_dist[(size_t)BB*NN*NN];         // 315 MB distance matrix
__device__ int   g_idx[(size_t)BB*NN*KNB];         // top-K neighbor indices
__device__ float g_feat[(size_t)BB*NN*2*CCH];      // interleaved (x, maxrel)
__device__ float g_y[(size_t)BB*NN*OUTC];          // pre-BN conv output
__device__ float g_psum[MB64*OUTC];                // BN partial sums
__device__ float g_psq[MB64*OUTC];                 // BN partial sumsq
__device__ float g_scale[OUTC];
__device__ float g_shift[OUTC];

// ---------------- 1) transpose x (B,C,N) -> xt (B,N,C) ----------------
__global__ void k_transpose(const float* __restrict__ x) {
    __shared__ float tile[32][33];
    int b  = blockIdx.z;
    int n0 = blockIdx.x * 32, c0 = blockIdx.y * 32;
    int tx = threadIdx.x, ty = threadIdx.y;
    tile[ty][tx] = x[((size_t)b*CCH + c0 + ty)*NN + n0 + tx];
    __syncthreads();
    g_xt[((size_t)b*NN + n0 + ty)*CCH + c0 + tx] = tile[tx][ty];
}

// ---------------- 2) row squared norms ----------------
__global__ void k_x2() {
    int row  = blockIdx.x * 8 + (threadIdx.x >> 5);
    int lane = threadIdx.x & 31;
    const float* p = g_xt + (size_t)row * CCH;
    float s = 0.f;
    for (int c = lane; c < CCH; c += 32) { float v = p[c]; s += v * v; }
    #pragma unroll
    for (int o = 16; o; o >>= 1) s += __shfl_down_sync(FULLM, s, o);
    if (lane == 0) g_x2[row] = s;
}

// ---------------- 3) symmetric distance GEMM ----------------
__global__ void k_dist() {
    int b = blockIdx.y;
    int p = blockIdx.x;
    int ti = 0, rem = p;
    while (rem >= NT64 - ti) { rem -= NT64 - ti; ti++; }
    int tj = ti + rem;
    int i0 = ti * 64, j0 = tj * 64;

    __shared__ __align__(16) float As[16][64];
    __shared__ __align__(16) float Bs[16][64];
    __shared__ float Ts[64][65];

    int tid = threadIdx.x;
    int tx = tid & 15, ty = tid >> 4;

    float acc[8][4];
    #pragma unroll
    for (int r = 0; r < 8; r++)
        #pragma unroll
        for (int c = 0; c < 4; c++) acc[r][c] = 0.f;

    const float* xa = g_xt + (size_t)b * NN * CCH;

    for (int kk = 0; kk < CCH; kk += 16) {
        #pragma unroll
        for (int e = 0; e < 2; e++) {
            int q = tid + e * 128;
            int m = q >> 2, k4 = (q & 3) << 2;
            float4 va = *(const float4*)(xa + (size_t)(i0 + m)*CCH + kk + k4);
            As[k4+0][m] = va.x; As[k4+1][m] = va.y; As[k4+2][m] = va.z; As[k4+3][m] = va.w;
            float4 vb = *(const float4*)(xa + (size_t)(j0 + m)*CCH + kk + k4);
            Bs[k4+0][m] = vb.x; Bs[k4+1][m] = vb.y; Bs[k4+2][m] = vb.z; Bs[k4+3][m] = vb.w;
        }
        __syncthreads();
        #pragma unroll
        for (int k = 0; k < 16; k++) {
            float4 a0 = *(const float4*)&As[k][ty*8];
            float4 a1 = *(const float4*)&As[k][ty*8+4];
            float4 b0 = *(const float4*)&Bs[k][tx*4];
            float a[8] = {a0.x,a0.y,a0.z,a0.w,a1.x,a1.y,a1.z,a1.w};
            float bv[4] = {b0.x,b0.y,b0.z,b0.w};
            #pragma unroll
            for (int r = 0; r < 8; r++)
                #pragma unroll
                for (int c = 0; c < 4; c++) acc[r][c] += a[r]*bv[c];
        }
        __syncthreads();
    }

    float x2i[8], x2j[4];
    #pragma unroll
    for (int r = 0; r < 8; r++) x2i[r] = g_x2[b*NN + i0 + ty*8 + r];
    #pragma unroll
    for (int c = 0; c < 4; c++) x2j[c] = g_x2[b*NN + j0 + tx*4 + c];

    #pragma unroll
    for (int r = 0; r < 8; r++) {
        #pragma unroll
        for (int c = 0; c < 4; c++) {
            float d = x2i[r] + x2j[c] - 2.f * acc[r][c];
            g_dist[((size_t)b*NN + i0 + ty*8 + r)*NN + j0 + tx*4 + c] = d;
            Ts[tx*4 + c][ty*8 + r] = d;
        }
    }
    if (ti != tj) {
        __syncthreads();
        #pragma unroll
        for (int e = 0; e < 32; e++) {
            int q = tid + e * 128;
            int r = q >> 6, cc = q & 63;
            g_dist[((size_t)b*NN + j0 + r)*NN + i0 + cc] = Ts[r][cc];
        }
    }
}

// ---------------- 4) top-K: two-pass threshold select (warp per row) ----------------
// Pass 1: per-lane 2 smallest values (registers) -> warp-pop 16 -> threshold tau
//         (tau >= true 16th smallest since union is a subset of the row).
// Pass 2: ballot-compact all d <= tau into per-warp shared queue, then 16 exact
//         argmin rounds with (value, index) lexicographic tie-break.
__global__ void k_topk() {
    __shared__ float qv[8][QCAP];
    __shared__ int   qi[8][QCAP];
    int w = threadIdx.x >> 5, lane = threadIdx.x & 31;
    int row = blockIdx.x * 8 + w;
    const float4* dr4 = (const float4*)(g_dist + (size_t)row * NN);
    unsigned lmask_lt = (1u << lane) - 1u;

    // ---- Pass 1: per-lane two smallest (values only) ----
    float a0 = CUDART_INF_F, a1 = CUDART_INF_F;
    const int NQ = NN / 4;            // 784 quads
    for (int i = 0; i < (NQ + 31) / 32; i++) {
        int q = i * 32 + lane;
        if (q < NQ) {
            float4 v = dr4[q];
            float m01 = fminf(v.x, v.y), m23 = fminf(v.z, v.w);
            float mq = fminf(m01, m23);
            if (mq < a1) {
                #pragma unroll
                for (int c = 0; c < 4; c++) {
                    float d = (c == 0) ? v.x : (c == 1) ? v.y : (c == 2) ? v.z : v.w;
                    if (d < a1) { if (d < a0) { a1 = a0; a0 = d; } else a1 = d; }
                }
            }
        }
    }

    // ---- pop 16 smallest from union of per-lane pairs -> tau ----
    // Bounded to 16 iterations (each iteration pops >=1); tau is the last
    // popped value, i.e. the 16th-smallest (or larger on the final partial pop).
    float h0 = a0, h1 = a1;
    float tau = CUDART_INF_F;
    int popped = 0;
    #pragma unroll 1
    for (int it = 0; it < KNB && popped < KNB; it++) {
        float m = h0;
        #pragma unroll
        for (int o = 16; o; o >>= 1) m = fminf(m, __shfl_down_sync(FULLM, m, o));
        m = __shfl_sync(FULLM, m, 0);
        unsigned hit = __ballot_sync(FULLM, h0 == m);
        popped += __popc(hit);
        tau = m;
        if (h0 == m) { h0 = h1; h1 = CUDART_INF_F; }
    }

    // ---- Pass 2: compact candidates (d <= tau) into shared queue ----
    float* myqv = qv[w];
    int*   myqi = qi[w];
    int cnt = 0;
    for (int i = 0; i < (NQ + 31) / 32; i++) {
        int q = i * 32 + lane;
        bool valid = q < NQ;
        float4 v = valid ? dr4[q] : make_float4(CUDART_INF_F, CUDART_INF_F, CUDART_INF_F, CUDART_INF_F);
        float mq = fminf(fminf(v.x, v.y), fminf(v.z, v.w));
        unsigned anyb = __ballot_sync(FULLM, mq <= tau);
        if (anyb == 0) continue;
        #pragma unroll
        for (int c = 0; c < 4; c++) {
            float d = (c == 0) ? v.x : (c == 1) ? v.y : (c == 2) ? v.z : v.w;
            bool h = d <= tau;
            unsigned bm = __ballot_sync(FULLM, h);
            if (h) {
                int pos = cnt + __popc(bm & lmask_lt);
                if (pos < QCAP) { myqv[pos] = d; myqi[pos] = q * 4 + c; }
            }
            cnt += __popc(bm);
        }
    }
    if (cnt > QCAP) cnt = QCAP;
    __syncwarp();

    // ---- exact selection: 16 rounds of lexicographic argmin over queue ----
    float bv = CUDART_INF_F; int bi = 0x7fffffff, bp = -1;
    for (int p = lane; p < cnt; p += 32) {
        float v = myqv[p]; int ix = myqi[p];
        if (v < bv || (v == bv && ix < bi)) { bv = v; bi = ix; bp = p; }
    }
    for (int k = 0; k < KNB; k++) {
        float rv = bv; int ri = bi, rp = bp, rl = lane;
        #pragma unroll
        for (int o = 16; o; o >>= 1) {
            float ov = __shfl_down_sync(FULLM, rv, o);
            int   oi = __shfl_down_sync(FULLM, ri, o);
            int   op = __shfl_down_sync(FULLM, rp, o);
            int   ol = __shfl_down_sync(FULLM, rl, o);
            if (ov < rv || (ov == rv && oi < ri)) { rv = ov; ri = oi; rp = op; rl = ol; }
        }
        int wi = __shfl_sync(FULLM, ri, 0);
        int wp = __shfl_sync(FULLM, rp, 0);
        int wl = __shfl_sync(FULLM, rl, 0);
        if (lane == 0) g_idx[(size_t)row * KNB + k] = wi;
        if (lane == wl) {
            myqv[wp] = CUDART_INF_F;
            // rescan this lane's stripe
            bv = CUDART_INF_F; bi = 0x7fffffff; bp = -1;
            for (int p = lane; p < cnt; p += 32) {
                float v = myqv[p]; int ix = myqi[p];
                if (v < bv || (v == bv && ix < bi)) { bv = v; bi = ix; bp = p; }
            }
        }
        __syncwarp();
    }
}

// ---------------- 5) gather + max-relative + interleaved feat ----------------
__global__ void k_feat() {
    __shared__ int ji[KNB];
    int m = blockIdx.x;          // b*N + n
    int c = threadIdx.x;         // 192 threads
    if (c < KNB) ji[c] = g_idx[(size_t)m*KNB + c];
    __syncthreads();
    int b = m / NN;
    const float* xb = g_xt + (size_t)b * NN * CCH;
    float xc = g_xt[(size_t)m*CCH + c];
    float mx = -CUDART_INF_F;
    #pragma unroll
    for (int k = 0; k < KNB; k++) {
        float v = xb[(size_t)ji[k]*CCH + c];
        mx = fmaxf(mx, v - xc);
    }
    float2 o; o.x = xc; o.y = mx;
    *(float2*)&g_feat[(size_t)m*(2*CCH) + 2*c] = o;
}

// ---------------- 6) y = feat @ w^T + bias ----------------
__global__ void k_gemm2(const float* __restrict__ w, const float* __restrict__ bias) {
    int m0 = blockIdx.x * 64;
    int o0 = blockIdx.y * 64;
    __shared__ __align__(16) float As[16][64];
    __shared__ __align__(16) float Bs[16][64];
    int tid = threadIdx.x;
    int tx = tid & 15, ty = tid >> 4;
    float acc[8][4];
    #pragma unroll
    for (int r = 0; r < 8; r++)
        #pragma unroll
        for (int c = 0; c < 4; c++) acc[r][c] = 0.f;

    for (int kk = 0; kk < 2*CCH; kk += 16) {
        #pragma unroll
        for (int e = 0; e < 2; e++) {
            int q = tid + e * 128;
            int m = q >> 2, k4 = (q & 3) << 2;
            float4 va = *(const float4*)(g_feat + (size_t)(m0 + m)*(2*CCH) + kk + k4);
            As[k4+0][m] = va.x; As[k4+1][m] = va.y; As[k4+2][m] = va.z; As[k4+3][m] = va.w;
            float4 vb = *(const float4*)(w + (size_t)(o0 + m)*(2*CCH) + kk + k4);
            Bs[k4+0][m] = vb.x; Bs[k4+1][m] = vb.y; Bs[k4+2][m] = vb.z; Bs[k4+3][m] = vb.w;
        }
        __syncthreads();
        #pragma unroll
        for (int k = 0; k < 16; k++) {
            float4 a0 = *(const float4*)&As[k][ty*8];
            float4 a1 = *(const float4*)&As[k][ty*8+4];
            float4 b0 = *(const float4*)&Bs[k][tx*4];
            float a[8] = {a0.x,a0.y,a0.z,a0.w,a1.x,a1.y,a1.z,a1.w};
            float bv[4] = {b0.x,b0.y,b0.z,b0.w};
            #pragma unroll
            for (int r = 0; r < 8; r++)
                #pragma unroll
                for (int c = 0; c < 4; c++) acc[r][c] += a[r]*bv[c];
        }
        __syncthreads();
    }
    #pragma unroll
    for (int r = 0; r < 8; r++) {
        #pragma unroll
        for (int c = 0; c < 4; c++) {
            int o = o0 + tx*4 + c;
            g_y[(size_t)(m0 + ty*8 + r)*OUTC + o] = acc[r][c] + bias[o];
        }
    }
}

// ---------------- 7) BN partial sums (deterministic, no atomics) ----------------
__global__ void k_bnpart() {
    int o  = threadIdx.x;        // 384 threads
    int m0 = blockIdx.x * 64;    // 392 blocks
    float s = 0.f, q = 0.f;
    for (int r = 0; r < 64; r++) {
        float v = g_y[(size_t)(m0 + r)*OUTC + o];
        s += v; q += v * v;
    }
    g_psum[blockIdx.x*OUTC + o] = s;
    g_psq [blockIdx.x*OUTC + o] = q;
}

// ---------------- 8) BN finalize -> scale/shift ----------------
__global__ void k_bnfin(const float* __restrict__ gamma, const float* __restrict__ beta) {
    __shared__ float ss[256], sq[256];
    int o = blockIdx.x, t = threadIdx.x;
    float s = 0.f, q = 0.f;
    for (int p = t; p < MB64; p += 256) { s += g_psum[p*OUTC + o]; q += g_psq[p*OUTC + o]; }
    ss[t] = s; sq[t] = q; __syncthreads();
    for (int st = 128; st; st >>= 1) {
        if (t < st) { ss[t] += ss[t+st]; sq[t] += sq[t+st]; }
        __syncthreads();
    }
    if (t == 0) {
        float mean = ss[0] / (float)MTOT;
        float var  = sq[0] / (float)MTOT - mean*mean;
        float rs   = rsqrtf(var + 1e-5f);
        float sc   = gamma[o] * rs;
        g_scale[o] = sc;
        g_shift[o] = beta[o] - mean * sc;
    }
}

// ---------------- 9) normalize + ReLU + transpose to (B,OUT,N) ----------------
__global__ void k_out(float* __restrict__ out) {
    __shared__ float tile[32][33];
    int b  = blockIdx.z;
    int n0 = blockIdx.x * 32, o0 = blockIdx.y * 32;
    int tx = threadIdx.x, ty = threadIdx.y;
    int o = o0 + tx;
    float v = g_y[(size_t)(b*NN + n0 + ty)*OUTC + o];
    v = v * g_scale[o] + g_shift[o];
    tile[ty][tx] = fmaxf(v, 0.f);
    __syncthreads();
    out[((size_t)b*OUTC + o0 + ty)*NN + n0 + tx] = tile[tx][ty];
}

// ---------------- launch ----------------
extern "C" void kernel_launch(void* const* d_in, const int* in_sizes, int n_in,
                              void* d_out, int out_size) {
    const float* x     = (const float*)d_in[0];
    const float* w     = (const float*)d_in[1];
    const float* bias  = (const float*)d_in[2];
    const float* gamma = (const float*)d_in[3];
    const float* beta  = (const float*)d_in[4];
    float* out = (float*)d_out;

    dim3 tposeGrid(NN/32, CCH/32, BB);
    k_transpose<<<tposeGrid, dim3(32,32)>>>(x);
    k_x2<<<MTOT/8, 256>>>();
    k_dist<<<dim3(NPAIR, BB), 128>>>();
    k_topk<<<MTOT/8, 256>>>();
    k_feat<<<MTOT, CCH>>>();
    k_gemm2<<<dim3(MTOT/64, OUTC/64), 128>>>(w, bias);
    k_bnpart<<<MB64, OUTC>>>();
    k_bnfin<<<OUTC, 256>>>(gamma, beta);
    k_out<<<dim3(NN/32, OUTC/32, BB), dim3(32,32)>>>(out);
}

// round 7
// speedup vs baseline: 1.4649x; 1.0111x over previous
#include <cuda_runtime.h>
#include <math_constants.h>
#include <cstdint>

#define BB   8
#define CCH  192
#define OUTC 384
#define NN   3136            // H*W = 56*56
#define KNB  16
#define MTOT (BB*NN)         // 25088
#define NT64 (NN/64)         // 49 tiles per dim
#define NPAIR ((NT64*(NT64+1))/2)   // 1225 upper-tri tile pairs
#define MB64 (MTOT/64)       // 392
#define QCAP 512             // per-warp candidate queue capacity
#define FULLM 0xffffffffu

typedef unsigned long long u64;

// packed f32x2 helpers (sm_100a)
__device__ __forceinline__ u64 pack2(float x, float y) {
    u64 r; asm("mov.b64 %0, {%1, %2};" : "=l"(r) : "f"(x), "f"(y)); return r;
}
__device__ __forceinline__ void unpack2(u64 p, float& x, float& y) {
    asm("mov.b64 {%0, %1}, %2;" : "=f"(x), "=f"(y) : "l"(p));
}
__device__ __forceinline__ void fma2(u64& d, u64 a, u64 b) {
    asm("fma.rn.f32x2 %0, %1, %2, %0;" : "+l"(d) : "l"(a), "l"(b));
}

// ---------------- device scratch (no allocs allowed) ----------------
__device__ float g_xt[(size_t)BB*NN*CCH];          // (B,N,C) transposed features
__device__ float g_x2[BB*NN];                      // row squared norms
__device__ float g_dist[(size_t)BB*NN*NN];         // 315 MB distance matrix
__device__ int   g_idx[(size_t)BB*NN*KNB];         // top-K neighbor indices
__device__ float g_feat[(size_t)BB*NN*2*CCH];      // interleaved (x, maxrel)
__device__ float g_y[(size_t)BB*NN*OUTC];          // pre-BN conv output
__device__ float g_psum[MB64*OUTC];                // BN partial sums
__device__ float g_psq[MB64*OUTC];                 // BN partial sumsq
__device__ float g_scale[OUTC];
__device__ float g_shift[OUTC];

// ---------------- 1) transpose x (B,C,N) -> xt (B,N,C) ----------------
__global__ void k_transpose(const float* __restrict__ x) {
    __shared__ float tile[32][33];
    int b  = blockIdx.z;
    int n0 = blockIdx.x * 32, c0 = blockIdx.y * 32;
    int tx = threadIdx.x, ty = threadIdx.y;
    tile[ty][tx] = x[((size_t)b*CCH + c0 + ty)*NN + n0 + tx];
    __syncthreads();
    g_xt[((size_t)b*NN + n0 + ty)*CCH + c0 + tx] = tile[tx][ty];
}

// ---------------- 2) row squared norms ----------------
__global__ void k_x2() {
    int row  = blockIdx.x * 8 + (threadIdx.x >> 5);
    int lane = threadIdx.x & 31;
    const float* p = g_xt + (size_t)row * CCH;
    float s = 0.f;
    for (int c = lane; c < CCH; c += 32) { float v = p[c]; s += v * v; }
    #pragma unroll
    for (int o = 16; o; o >>= 1) s += __shfl_down_sync(FULLM, s, o);
    if (lane == 0) g_x2[row] = s;
}

// ---------------- 3) symmetric distance GEMM (f32x2 packed FMA) ----------------
// 64x64 tile, 128 threads, 8x4 microtile; accumulators packed along row pairs.
__global__ void k_dist() {
    int b = blockIdx.y;
    int p = blockIdx.x;
    int ti = 0, rem = p;
    while (rem >= NT64 - ti) { rem -= NT64 - ti; ti++; }
    int tj = ti + rem;
    int i0 = ti * 64, j0 = tj * 64;

    __shared__ __align__(16) float As[16][64];
    __shared__ __align__(16) float Bs[16][64];
    __shared__ float Ts[64][65];

    int tid = threadIdx.x;
    int tx = tid & 15, ty = tid >> 4;

    u64 accp[4][4];
    #pragma unroll
    for (int i = 0; i < 4; i++)
        #pragma unroll
        for (int c = 0; c < 4; c++) accp[i][c] = 0ull;

    const float* xa = g_xt + (size_t)b * NN * CCH;

    for (int kk = 0; kk < CCH; kk += 16) {
        #pragma unroll
        for (int e = 0; e < 2; e++) {
            int q = tid + e * 128;
            int m = q >> 2, k4 = (q & 3) << 2;
            float4 va = *(const float4*)(xa + (size_t)(i0 + m)*CCH + kk + k4);
            As[k4+0][m] = va.x; As[k4+1][m] = va.y; As[k4+2][m] = va.z; As[k4+3][m] = va.w;
            float4 vb = *(const float4*)(xa + (size_t)(j0 + m)*CCH + kk + k4);
            Bs[k4+0][m] = vb.x; Bs[k4+1][m] = vb.y; Bs[k4+2][m] = vb.z; Bs[k4+3][m] = vb.w;
        }
        __syncthreads();
        #pragma unroll
        for (int k = 0; k < 16; k++) {
            u64 a01[4];
            #pragma unroll
            for (int i = 0; i < 4; i++)
                a01[i] = *(const u64*)&As[k][ty*8 + 2*i];
            float4 bq = *(const float4*)&Bs[k][tx*4];
            u64 bb[4] = { pack2(bq.x, bq.x), pack2(bq.y, bq.y),
                          pack2(bq.z, bq.z), pack2(bq.w, bq.w) };
            #pragma unroll
            for (int i = 0; i < 4; i++)
                #pragma unroll
                for (int c = 0; c < 4; c++) fma2(accp[i][c], a01[i], bb[c]);
        }
        __syncthreads();
    }

    float acc[8][4];
    #pragma unroll
    for (int i = 0; i < 4; i++)
        #pragma unroll
        for (int c = 0; c < 4; c++)
            unpack2(accp[i][c], acc[2*i][c], acc[2*i+1][c]);

    float x2i[8], x2j[4];
    #pragma unroll
    for (int r = 0; r < 8; r++) x2i[r] = g_x2[b*NN + i0 + ty*8 + r];
    #pragma unroll
    for (int c = 0; c < 4; c++) x2j[c] = g_x2[b*NN + j0 + tx*4 + c];

    #pragma unroll
    for (int r = 0; r < 8; r++) {
        #pragma unroll
        for (int c = 0; c < 4; c++) {
            float d = x2i[r] + x2j[c] - 2.f * acc[r][c];
            g_dist[((size_t)b*NN + i0 + ty*8 + r)*NN + j0 + tx*4 + c] = d;
            Ts[tx*4 + c][ty*8 + r] = d;
        }
    }
    if (ti != tj) {
        __syncthreads();
        #pragma unroll
        for (int e = 0; e < 32; e++) {
            int q = tid + e * 128;
            int r = q >> 6, cc = q & 63;
            g_dist[((size_t)b*NN + j0 + r)*NN + i0 + cc] = Ts[r][cc];
        }
    }
}

// ---------------- 4) top-K: two-pass threshold select (warp per row) ----------------
__global__ void k_topk() {
    __shared__ float qv[8][QCAP];
    __shared__ int   qi[8][QCAP];
    int w = threadIdx.x >> 5, lane = threadIdx.x & 31;
    int row = blockIdx.x * 8 + w;
    const float4* dr4 = (const float4*)(g_dist + (size_t)row * NN);
    unsigned lmask_lt = (1u << lane) - 1u;

    // ---- Pass 1: per-lane two smallest (values only) ----
    float a0 = CUDART_INF_F, a1 = CUDART_INF_F;
    const int NQ = NN / 4;            // 784 quads
    for (int i = 0; i < (NQ + 31) / 32; i++) {
        int q = i * 32 + lane;
        if (q < NQ) {
            float4 v = dr4[q];
            float m01 = fminf(v.x, v.y), m23 = fminf(v.z, v.w);
            float mq = fminf(m01, m23);
            if (mq < a1) {
                #pragma unroll
                for (int c = 0; c < 4; c++) {
                    float d = (c == 0) ? v.x : (c == 1) ? v.y : (c == 2) ? v.z : v.w;
                    if (d < a1) { if (d < a0) { a1 = a0; a0 = d; } else a1 = d; }
                }
            }
        }
    }

    // ---- pop 16 smallest from union of per-lane pairs -> tau (bounded) ----
    float h0 = a0, h1 = a1;
    float tau = CUDART_INF_F;
    int popped = 0;
    #pragma unroll 1
    for (int it = 0; it < KNB && popped < KNB; it++) {
        float m = h0;
        #pragma unroll
        for (int o = 16; o; o >>= 1) m = fminf(m, __shfl_down_sync(FULLM, m, o));
        m = __shfl_sync(FULLM, m, 0);
        unsigned hit = __ballot_sync(FULLM, h0 == m);
        popped += __popc(hit);
        tau = m;
        if (h0 == m) { h0 = h1; h1 = CUDART_INF_F; }
    }

    // ---- Pass 2: compact candidates (d <= tau) into shared queue ----
    float* myqv = qv[w];
    int*   myqi = qi[w];
    int cnt = 0;
    for (int i = 0; i < (NQ + 31) / 32; i++) {
        int q = i * 32 + lane;
        bool valid = q < NQ;
        float4 v = valid ? dr4[q] : make_float4(CUDART_INF_F, CUDART_INF_F, CUDART_INF_F, CUDART_INF_F);
        float mq = fminf(fminf(v.x, v.y), fminf(v.z, v.w));
        unsigned anyb = __ballot_sync(FULLM, mq <= tau);
        if (anyb == 0) continue;
        #pragma unroll
        for (int c = 0; c < 4; c++) {
            float d = (c == 0) ? v.x : (c == 1) ? v.y : (c == 2) ? v.z : v.w;
            bool h = d <= tau;
            unsigned bm = __ballot_sync(FULLM, h);
            if (h) {
                int pos = cnt + __popc(bm & lmask_lt);
                if (pos < QCAP) { myqv[pos] = d; myqi[pos] = q * 4 + c; }
            }
            cnt += __popc(bm);
        }
    }
    if (cnt > QCAP) cnt = QCAP;
    __syncwarp();

    // ---- exact selection: 16 rounds of lexicographic argmin over queue ----
    float bv = CUDART_INF_F; int bi = 0x7fffffff, bp = -1;
    for (int p = lane; p < cnt; p += 32) {
        float v = myqv[p]; int ix = myqi[p];
        if (v < bv || (v == bv && ix < bi)) { bv = v; bi = ix; bp = p; }
    }
    for (int k = 0; k < KNB; k++) {
        float rv = bv; int ri = bi, rp = bp, rl = lane;
        #pragma unroll
        for (int o = 16; o; o >>= 1) {
            float ov = __shfl_down_sync(FULLM, rv, o);
            int   oi = __shfl_down_sync(FULLM, ri, o);
            int   op = __shfl_down_sync(FULLM, rp, o);
            int   ol = __shfl_down_sync(FULLM, rl, o);
            if (ov < rv || (ov == rv && oi < ri)) { rv = ov; ri = oi; rp = op; rl = ol; }
        }
        int wi = __shfl_sync(FULLM, ri, 0);
        int wp = __shfl_sync(FULLM, rp, 0);
        int wl = __shfl_sync(FULLM, rl, 0);
        if (lane == 0) g_idx[(size_t)row * KNB + k] = wi;
        if (lane == wl) {
            myqv[wp] = CUDART_INF_F;
            bv = CUDART_INF_F; bi = 0x7fffffff; bp = -1;
            for (int p = lane; p < cnt; p += 32) {
                float v = myqv[p]; int ix = myqi[p];
                if (v < bv || (v == bv && ix < bi)) { bv = v; bi = ix; bp = p; }
            }
        }
        __syncwarp();
    }
}

// ---------------- 5) gather + max-relative + interleaved feat ----------------
__global__ void k_feat() {
    __shared__ int ji[KNB];
    int m = blockIdx.x;          // b*N + n
    int c = threadIdx.x;         // 192 threads
    if (c < KNB) ji[c] = g_idx[(size_t)m*KNB + c];
    __syncthreads();
    int b = m / NN;
    const float* xb = g_xt + (size_t)b * NN * CCH;
    float xc = g_xt[(size_t)m*CCH + c];
    float mx = -CUDART_INF_F;
    #pragma unroll
    for (int k = 0; k < KNB; k++) {
        float v = xb[(size_t)ji[k]*CCH + c];
        mx = fmaxf(mx, v - xc);
    }
    float2 o; o.x = xc; o.y = mx;
    *(float2*)&g_feat[(size_t)m*(2*CCH) + 2*c] = o;
}

// ---------------- 6) y = feat @ w^T + bias (f32x2 packed FMA) ----------------
__global__ void k_gemm2(const float* __restrict__ w, const float* __restrict__ bias) {
    int m0 = blockIdx.x * 64;
    int o0 = blockIdx.y * 64;
    __shared__ __align__(16) float As[16][64];
    __shared__ __align__(16) float Bs[16][64];
    int tid = threadIdx.x;
    int tx = tid & 15, ty = tid >> 4;

    u64 accp[4][4];
    #pragma unroll
    for (int i = 0; i < 4; i++)
        #pragma unroll
        for (int c = 0; c < 4; c++) accp[i][c] = 0ull;

    for (int kk = 0; kk < 2*CCH; kk += 16) {
        #pragma unroll
        for (int e = 0; e < 2; e++) {
            int q = tid + e * 128;
            int m = q >> 2, k4 = (q & 3) << 2;
            float4 va = *(const float4*)(g_feat + (size_t)(m0 + m)*(2*CCH) + kk + k4);
            As[k4+0][m] = va.x; As[k4+1][m] = va.y; As[k4+2][m] = va.z; As[k4+3][m] = va.w;
            float4 vb = *(const float4*)(w + (size_t)(o0 + m)*(2*CCH) + kk + k4);
            Bs[k4+0][m] = vb.x; Bs[k4+1][m] = vb.y; Bs[k4+2][m] = vb.z; Bs[k4+3][m] = vb.w;
        }
        __syncthreads();
        #pragma unroll
        for (int k = 0; k < 16; k++) {
            u64 a01[4];
            #pragma unroll
            for (int i = 0; i < 4; i++)
                a01[i] = *(const u64*)&As[k][ty*8 + 2*i];
            float4 bq = *(const float4*)&Bs[k][tx*4];
            u64 bb[4] = { pack2(bq.x, bq.x), pack2(bq.y, bq.y),
                          pack2(bq.z, bq.z), pack2(bq.w, bq.w) };
            #pragma unroll
            for (int i = 0; i < 4; i++)
                #pragma unroll
                for (int c = 0; c < 4; c++) fma2(accp[i][c], a01[i], bb[c]);
        }
        __syncthreads();
    }

    float acc[8][4];
    #pragma unroll
    for (int i = 0; i < 4; i++)
        #pragma unroll
        for (int c = 0; c < 4; c++)
            unpack2(accp[i][c], acc[2*i][c], acc[2*i+1][c]);

    #pragma unroll
    for (int r = 0; r < 8; r++) {
        #pragma unroll
        for (int c = 0; c < 4; c++) {
            int o = o0 + tx*4 + c;
            g_y[(size_t)(m0 + ty*8 + r)*OUTC + o] = acc[r][c] + bias[o];
        }
    }
}

// ---------------- 7) BN partial sums (deterministic, no atomics) ----------------
__global__ void k_bnpart() {
    int o  = threadIdx.x;        // 384 threads
    int m0 = blockIdx.x * 64;    // 392 blocks
    float s = 0.f, q = 0.f;
    for (int r = 0; r < 64; r++) {
        float v = g_y[(size_t)(m0 + r)*OUTC + o];
        s += v; q += v * v;
    }
    g_psum[blockIdx.x*OUTC + o] = s;
    g_psq [blockIdx.x*OUTC + o] = q;
}

// ---------------- 8) BN finalize -> scale/shift ----------------
__global__ void k_bnfin(const float* __restrict__ gamma, const float* __restrict__ beta) {
    __shared__ float ss[256], sq[256];
    int o = blockIdx.x, t = threadIdx.x;
    float s = 0.f, q = 0.f;
    for (int p = t; p < MB64; p += 256) { s += g_psum[p*OUTC + o]; q += g_psq[p*OUTC + o]; }
    ss[t] = s; sq[t] = q; __syncthreads();
    for (int st = 128; st; st >>= 1) {
        if (t < st) { ss[t] += ss[t+st]; sq[t] += sq[t+st]; }
        __syncthreads();
    }
    if (t == 0) {
        float mean = ss[0] / (float)MTOT;
        float var  = sq[0] / (float)MTOT - mean*mean;
        float rs   = rsqrtf(var + 1e-5f);
        float sc   = gamma[o] * rs;
        g_scale[o] = sc;
        g_shift[o] = beta[o] - mean * sc;
    }
}

// ---------------- 9) normalize + ReLU + transpose to (B,OUT,N) ----------------
__global__ void k_out(float* __restrict__ out) {
    __shared__ float tile[32][33];
    int b  = blockIdx.z;
    int n0 = blockIdx.x * 32, o0 = blockIdx.y * 32;
    int tx = threadIdx.x, ty = threadIdx.y;
    int o = o0 + tx;
    float v = g_y[(size_t)(b*NN + n0 + ty)*OUTC + o];
    v = v * g_scale[o] + g_shift[o];
    tile[ty][tx] = fmaxf(v, 0.f);
    __syncthreads();
    out[((size_t)b*OUTC + o0 + ty)*NN + n0 + tx] = tile[tx][ty];
}

// ---------------- launch ----------------
extern "C" void kernel_launch(void* const* d_in, const int* in_sizes, int n_in,
                              void* d_out, int out_size) {
    const float* x     = (const float*)d_in[0];
    const float* w     = (const float*)d_in[1];
    const float* bias  = (const float*)d_in[2];
    const float* gamma = (const float*)d_in[3];
    const float* beta  = (const float*)d_in[4];
    float* out = (float*)d_out;

    dim3 tposeGrid(NN/32, CCH/32, BB);
    k_transpose<<<tposeGrid, dim3(32,32)>>>(x);
    k_x2<<<MTOT/8, 256>>>();
    k_dist<<<dim3(NPAIR, BB), 128>>>();
    k_topk<<<MTOT/8, 256>>>();
    k_feat<<<MTOT, CCH>>>();
    k_gemm2<<<dim3(MTOT/64, OUTC/64), 128>>>(w, bias);
    k_bnpart<<<MB64, OUTC>>>();
    k_bnfin<<<OUTC, 256>>>(gamma, beta);
    k_out<<<dim3(NN/32, OUTC/32, BB), dim3(32,32)>>>(out);
}